// round 1
// baseline (speedup 1.0000x reference)
#include <cuda_runtime.h>
#include <math.h>

#define NUM_GRAPHS 8
#define NUM_PASSES 3
#define BN_MAX 400000
#define M_MAX 2048

__device__ float g_bufA[BN_MAX];
__device__ float g_bufB[BN_MAX];
__device__ float g_norms[NUM_GRAPHS];

__global__ void init_kernel(int BN) {
    int stride = gridDim.x * blockDim.x;
    for (int i = blockIdx.x * blockDim.x + threadIdx.x; i < BN; i += stride)
        g_bufB[i] = 0.0f;
}

__global__ void scatter_kernel(const float* __restrict__ h,
                               const int4* __restrict__ src4,
                               const int4* __restrict__ dst4,
                               const float4* __restrict__ ew4,
                               int nquad,
                               const int* __restrict__ src_s,
                               const int* __restrict__ dst_s,
                               const float* __restrict__ ew_s,
                               int ntail) {
    if (blockIdx.x == 0 && threadIdx.x < NUM_GRAPHS)
        g_norms[threadIdx.x] = 0.0f;

    int tid = blockIdx.x * blockDim.x + threadIdx.x;
    int stride = gridDim.x * blockDim.x;
    for (int i = tid; i < nquad; i += stride) {
        int4   s = src4[i];
        int4   d = dst4[i];
        float4 w = ew4[i];
        float m0 = __ldg(&h[s.x]) * log1pf(w.x);
        float m1 = __ldg(&h[s.y]) * log1pf(w.y);
        float m2 = __ldg(&h[s.z]) * log1pf(w.z);
        float m3 = __ldg(&h[s.w]) * log1pf(w.w);
        atomicAdd(&g_bufB[d.x], m0);
        atomicAdd(&g_bufB[d.y], m1);
        atomicAdd(&g_bufB[d.z], m2);
        atomicAdd(&g_bufB[d.w], m3);
    }
    if (tid < ntail) {
        int e = nquad * 4 + tid;
        float m = __ldg(&h[src_s[e]]) * log1pf(ew_s[e]);
        atomicAdd(&g_bufB[dst_s[e]], m);
    }
}

__global__ void norm_kernel(int N) {
    int b = blockIdx.y;
    const float* h = g_bufB + b * N;
    float s = 0.0f;
    int stride = gridDim.x * blockDim.x;
    for (int i = blockIdx.x * blockDim.x + threadIdx.x; i < N; i += stride) {
        float v = h[i];
        s += v * v;
    }
    #pragma unroll
    for (int off = 16; off > 0; off >>= 1)
        s += __shfl_down_sync(0xffffffffu, s, off);
    __shared__ float warp_s[32];
    int lane = threadIdx.x & 31, wid = threadIdx.x >> 5;
    if (lane == 0) warp_s[wid] = s;
    __syncthreads();
    if (wid == 0) {
        int nw = (blockDim.x + 31) >> 5;
        s = (lane < nw) ? warp_s[lane] : 0.0f;
        #pragma unroll
        for (int off = 16; off > 0; off >>= 1)
            s += __shfl_down_sync(0xffffffffu, s, off);
        if (lane == 0) atomicAdd(&g_norms[b], s);
    }
}

__global__ void scale_kernel(int N, int BN) {
    int stride = gridDim.x * blockDim.x;
    for (int i = blockIdx.x * blockDim.x + threadIdx.x; i < BN; i += stride) {
        float v = g_bufB[i];
        g_bufB[i] = 0.0f;
        g_bufA[i] = v * rsqrtf(g_norms[i / N]);
    }
}

__global__ void final_kernel(const int* __restrict__ dm,
                             const float* __restrict__ fc_w,
                             const float* __restrict__ fc_b,
                             float* __restrict__ out,
                             int N, int M) {
    __shared__ float sv[M_MAX];
    __shared__ float red_f[256];
    __shared__ float red_g[256];
    __shared__ float s_mean, s_inv_std, s_cnt;

    int b = blockIdx.x;
    int t = threadIdx.x;
    const float* h = g_bufA + b * N;

    for (int m = t; m < M; m += blockDim.x)
        sv[m] = h[dm[m]];
    __syncthreads();

    float sum = 0.0f, cnt = 0.0f;
    for (int m = t; m < M; m += blockDim.x) {
        float v = sv[m];
        if (v != 0.0f) { sum += v; cnt += 1.0f; }
    }
    red_f[t] = sum; red_g[t] = cnt;
    __syncthreads();
    for (int off = 128; off > 0; off >>= 1) {
        if (t < off) { red_f[t] += red_f[t + off]; red_g[t] += red_g[t + off]; }
        __syncthreads();
    }
    if (t == 0) {
        float c = red_g[0];
        s_cnt = c;
        s_mean = red_f[0] / c;
    }
    __syncthreads();
    float mean = s_mean;
    float cntv = s_cnt;

    float ss = 0.0f;
    for (int m = t; m < M; m += blockDim.x) {
        float v = sv[m];
        if (v != 0.0f) { float d = v - mean; ss += d * d; }
    }
    red_f[t] = ss;
    __syncthreads();
    for (int off = 128; off > 0; off >>= 1) {
        if (t < off) red_f[t] += red_f[t + off];
        __syncthreads();
    }
    if (t == 0) {
        float var = red_f[0] / fmaxf(cntv - 1.0f, 1.0f);
        s_inv_std = 1.0f / (sqrtf(var) + 1e-5f);
    }
    __syncthreads();
    float inv_std = s_inv_std;

    float ps = 0.0f;
    for (int m = t; m < M; m += blockDim.x) {
        float v = sv[m];
        if (v != 0.0f) ps += (v - mean) * inv_std;
    }
    red_f[t] = ps;
    __syncthreads();
    for (int off = 128; off > 0; off >>= 1) {
        if (t < off) red_f[t] += red_f[t + off];
        __syncthreads();
    }
    if (t == 0) {
        float pooled = red_f[0] / (float)M;
        float o = pooled * fc_w[0] + fc_b[0];
        out[b] = fmaxf(o, 0.0f);
    }
}

extern "C" void kernel_launch(void* const* d_in, const int* in_sizes, int n_in,
                              void* d_out, int out_size) {
    const float* x    = (const float*)d_in[0];
    const float* ew   = (const float*)d_in[1];
    const int*   src  = (const int*)d_in[2];
    const int*   dst  = (const int*)d_in[3];
    const int*   dm   = (const int*)d_in[4];
    const float* fc_w = (const float*)d_in[5];
    const float* fc_b = (const float*)d_in[6];
    float* out = (float*)d_out;

    int BN = in_sizes[0];
    int E  = in_sizes[1];
    int M  = in_sizes[4];
    int N  = BN / NUM_GRAPHS;

    // device address of g_bufA for pass>0 input (query, not allocation)
    static float* bufA_ptr = nullptr;
    if (bufA_ptr == nullptr) {
        void* p = nullptr;
        cudaGetSymbolAddress(&p, g_bufA);
        bufA_ptr = (float*)p;
    }

    int nquad = E / 4;
    int ntail = E - nquad * 4;

    const int T = 256;
    int init_blocks    = (BN + T - 1) / T;
    int scatter_blocks = (nquad + T - 1) / T;
    dim3 norm_grid(64, NUM_GRAPHS);
    int scale_blocks   = (BN + T - 1) / T;

    init_kernel<<<init_blocks, T>>>(BN);

    for (int p = 0; p < NUM_PASSES; p++) {
        const float* h_in = (p == 0) ? x : (const float*)bufA_ptr;
        scatter_kernel<<<scatter_blocks, T>>>(
            h_in, (const int4*)src, (const int4*)dst, (const float4*)ew,
            nquad, src, dst, ew, ntail);
        norm_kernel<<<norm_grid, T>>>(N);
        scale_kernel<<<scale_blocks, T>>>(N, BN);
    }

    final_kernel<<<NUM_GRAPHS, T>>>(dm, fc_w, fc_b, out, N, M);
}

// round 5
// speedup vs baseline: 1.1109x; 1.1109x over previous
#include <cuda_runtime.h>
#include <math.h>

#define NUM_GRAPHS 8
#define NUM_PASSES 3
#define BN_MAX 400000
#define E_MAX 8000000
#define M_MAX 2048
#define SCATTER_GRID 1184   // 148 SMs * 8 blocks
#define SCATTER_T 256

// Allocation-free scratch
__device__ float g_lew[E_MAX];    // log1p(edge_weight), computed once per call
__device__ float g_A[BN_MAX];
__device__ float g_B[BN_MAX];
__device__ float g_C[BN_MAX];

// ---------------------------------------------------------------------------
// Init: lew = log1p(ew); zero all three accumulation buffers.
__global__ void init_kernel(const float* __restrict__ ew, int E, int BN) {
    int tid = blockIdx.x * blockDim.x + threadIdx.x;
    int stride = gridDim.x * blockDim.x;
    int nq = E >> 2;
    float4* lew4 = (float4*)g_lew;
    const float4* ew4 = (const float4*)ew;
    for (int i = tid; i < nq; i += stride) {
        float4 w = ew4[i];
        float4 o;
        o.x = log1pf(w.x); o.y = log1pf(w.y);
        o.z = log1pf(w.z); o.w = log1pf(w.w);
        lew4[i] = o;
    }
    for (int e = nq * 4 + tid; e < E; e += stride)
        g_lew[e] = log1pf(ew[e]);

    float4 z = make_float4(0.f, 0.f, 0.f, 0.f);
    int nb = BN >> 2;
    float4* A4 = (float4*)g_A; float4* B4 = (float4*)g_B; float4* C4 = (float4*)g_C;
    for (int i = tid; i < nb; i += stride) { A4[i] = z; B4[i] = z; C4[i] = z; }
    for (int i = nb * 4 + tid; i < BN; i += stride) { g_A[i] = 0.f; g_B[i] = 0.f; g_C[i] = 0.f; }
}

// ---------------------------------------------------------------------------
// Raw scatter pass: out[dst] += h[src] * lew  (no normalization — it cancels
// through the linear scatter; applied once in final_kernel where the +1e-5
// epsilon makes absolute scale matter).
// Blocks get contiguous quad slabs; swizzle so the blocks co-resident on one
// SM (bid % 148 -> same SM under classic placement) cover a contiguous edge
// range => src gathers hit a ~200KB (one-graph) working set that fits L1D.
__global__ __launch_bounds__(SCATTER_T, 8)
void scatter_kernel(const float* __restrict__ h,
                    float* __restrict__ out,
                    const int4* __restrict__ src4,
                    const int4* __restrict__ dst4,
                    const float4* __restrict__ lew4,
                    int nquad, int qper,
                    const int* __restrict__ src_s,
                    const int* __restrict__ dst_s,
                    int ntail) {
    int slab = (blockIdx.x % 148) * 8 + (blockIdx.x / 148);
    int q0 = slab * qper;
    int q1 = q0 + qper;
    if (q1 > nquad) q1 = nquad;

    for (int i = q0 + threadIdx.x; i < q1; i += SCATTER_T) {
        int4   s = src4[i];
        int4   d = dst4[i];
        float4 w = lew4[i];
        atomicAdd(&out[d.x], h[s.x] * w.x);
        atomicAdd(&out[d.y], h[s.y] * w.y);
        atomicAdd(&out[d.z], h[s.z] * w.z);
        atomicAdd(&out[d.w], h[s.w] * w.w);
    }
    // scalar tail (E not divisible by 4)
    if (blockIdx.x == 0 && threadIdx.x < ntail) {
        int e = nquad * 4 + threadIdx.x;
        atomicAdd(&out[dst_s[e]], h[src_s[e]] * g_lew[e]);
    }
}

// ---------------------------------------------------------------------------
// Final: per graph (one block each): sumsq-reduce g_C over N nodes -> scale,
// gather decision neurons (scaled), nonzero-masked standardization, mean pool,
// linear + relu.
__global__ void final_kernel(const int* __restrict__ dm,
                             const float* __restrict__ fc_w,
                             const float* __restrict__ fc_b,
                             float* __restrict__ out,
                             int N, int M) {
    __shared__ float sv[M_MAX];
    __shared__ float red_f[256];
    __shared__ float red_g[256];
    __shared__ float s_scale, s_mean, s_inv_std, s_cnt;

    int b = blockIdx.x;
    int t = threadIdx.x;
    const float* h = g_C + b * N;

    // Phase 0: per-graph sum of squares (vectorized)
    float ss = 0.0f;
    int n4 = N >> 2;
    const float4* h4 = (const float4*)h;
    for (int i = t; i < n4; i += blockDim.x) {
        float4 v = h4[i];
        ss += v.x * v.x + v.y * v.y + v.z * v.z + v.w * v.w;
    }
    for (int i = n4 * 4 + t; i < N; i += blockDim.x) { float v = h[i]; ss += v * v; }
    red_f[t] = ss;
    __syncthreads();
    for (int off = 128; off > 0; off >>= 1) {
        if (t < off) red_f[t] += red_f[t + off];
        __syncthreads();
    }
    if (t == 0) s_scale = rsqrtf(red_f[0]);
    __syncthreads();
    float scale = s_scale;

    // Gather decision neurons, scaled by the (only surviving) normalization
    for (int m = t; m < M; m += blockDim.x)
        sv[m] = h[dm[m]] * scale;
    __syncthreads();

    // Reduction 1: nonzero count + sum
    float sum = 0.0f, cnt = 0.0f;
    for (int m = t; m < M; m += blockDim.x) {
        float v = sv[m];
        if (v != 0.0f) { sum += v; cnt += 1.0f; }
    }
    red_f[t] = sum; red_g[t] = cnt;
    __syncthreads();
    for (int off = 128; off > 0; off >>= 1) {
        if (t < off) { red_f[t] += red_f[t + off]; red_g[t] += red_g[t + off]; }
        __syncthreads();
    }
    if (t == 0) { s_cnt = red_g[0]; s_mean = red_f[0] / red_g[0]; }
    __syncthreads();
    float mean = s_mean, cntv = s_cnt;

    // Reduction 2: sum (v-mean)^2 over nonzeros
    float ss2 = 0.0f;
    for (int m = t; m < M; m += blockDim.x) {
        float v = sv[m];
        if (v != 0.0f) { float d = v - mean; ss2 += d * d; }
    }
    red_f[t] = ss2;
    __syncthreads();
    for (int off = 128; off > 0; off >>= 1) {
        if (t < off) red_f[t] += red_f[t + off];
        __syncthreads();
    }
    if (t == 0) {
        float var = red_f[0] / fmaxf(cntv - 1.0f, 1.0f);
        s_inv_std = 1.0f / (sqrtf(var) + 1e-5f);
    }
    __syncthreads();
    float inv_std = s_inv_std;

    // Reduction 3: sum of standardized values over nonzeros
    float ps = 0.0f;
    for (int m = t; m < M; m += blockDim.x) {
        float v = sv[m];
        if (v != 0.0f) ps += (v - mean) * inv_std;
    }
    red_f[t] = ps;
    __syncthreads();
    for (int off = 128; off > 0; off >>= 1) {
        if (t < off) red_f[t] += red_f[t + off];
        __syncthreads();
    }
    if (t == 0) {
        float pooled = red_f[0] / (float)M;
        float o = pooled * fc_w[0] + fc_b[0];
        out[b] = fmaxf(o, 0.0f);
    }
}

// ---------------------------------------------------------------------------
extern "C" void kernel_launch(void* const* d_in, const int* in_sizes, int n_in,
                              void* d_out, int out_size) {
    const float* x    = (const float*)d_in[0];
    const float* ew   = (const float*)d_in[1];
    const int*   src  = (const int*)d_in[2];
    const int*   dst  = (const int*)d_in[3];
    const int*   dm   = (const int*)d_in[4];
    const float* fc_w = (const float*)d_in[5];
    const float* fc_b = (const float*)d_in[6];
    float* out = (float*)d_out;

    int BN = in_sizes[0];
    int E  = in_sizes[1];
    int M  = in_sizes[4];
    int N  = BN / NUM_GRAPHS;

    // Device addresses of __device__ symbols (host-side &symbol is invalid!)
    static float *pA = nullptr, *pB = nullptr, *pC = nullptr, *pLEW = nullptr;
    if (pA == nullptr) {
        void* p;
        cudaGetSymbolAddress(&p, g_A);   pA   = (float*)p;
        cudaGetSymbolAddress(&p, g_B);   pB   = (float*)p;
        cudaGetSymbolAddress(&p, g_C);   pC   = (float*)p;
        cudaGetSymbolAddress(&p, g_lew); pLEW = (float*)p;
    }

    int nquad = E / 4;
    int ntail = E - nquad * 4;
    int qper  = (nquad + SCATTER_GRID - 1) / SCATTER_GRID;

    init_kernel<<<2048, 256>>>(ew, E, BN);

    // Raw (unnormalized) passes: normalization cancels through linear scatter.
    const float* srcbuf[NUM_PASSES + 1] = { x, pA, pB, pC };
    float*       dstbuf[NUM_PASSES]     = { pA, pB, pC };
    for (int p = 0; p < NUM_PASSES; p++) {
        scatter_kernel<<<SCATTER_GRID, SCATTER_T>>>(
            srcbuf[p], dstbuf[p],
            (const int4*)src, (const int4*)dst, (const float4*)pLEW,
            nquad, qper, src, dst, ntail);
    }

    final_kernel<<<NUM_GRAPHS, 256>>>(dm, fc_w, fc_b, out, N, M);
}

// round 8
// speedup vs baseline: 1.1214x; 1.0095x over previous
#include <cuda_runtime.h>
#include <math.h>

#define NUM_GRAPHS 8
#define NUM_PASSES 3
#define BN_MAX 400000
#define E_MAX 8000000
#define M_MAX 2048

// Allocation-free scratch
__device__ float g_lew[E_MAX];    // log1p(edge_weight), computed once per call
__device__ float g_A[BN_MAX];
__device__ float g_B[BN_MAX];
__device__ float g_C[BN_MAX];

// ---------------------------------------------------------------------------
// Init: lew = log1p(ew); zero all three accumulation buffers.
__global__ void init_kernel(const float* __restrict__ ew, int E, int BN) {
    int tid = blockIdx.x * blockDim.x + threadIdx.x;
    int stride = gridDim.x * blockDim.x;
    int nq = E >> 2;
    float4* lew4 = (float4*)g_lew;
    const float4* ew4 = (const float4*)ew;
    for (int i = tid; i < nq; i += stride) {
        float4 w = ew4[i];
        float4 o;
        o.x = log1pf(w.x); o.y = log1pf(w.y);
        o.z = log1pf(w.z); o.w = log1pf(w.w);
        lew4[i] = o;
    }
    for (int e = nq * 4 + tid; e < E; e += stride)
        g_lew[e] = log1pf(ew[e]);

    float4 z = make_float4(0.f, 0.f, 0.f, 0.f);
    int nb = BN >> 2;
    float4* A4 = (float4*)g_A; float4* B4 = (float4*)g_B; float4* C4 = (float4*)g_C;
    for (int i = tid; i < nb; i += stride) { A4[i] = z; B4[i] = z; C4[i] = z; }
    for (int i = nb * 4 + tid; i < BN; i += stride) { g_A[i] = 0.f; g_B[i] = 0.f; g_C[i] = 0.f; }
}

// ---------------------------------------------------------------------------
// Raw scatter pass: out[dst] += h[src] * lew.  Normalization cancels through
// the linear scatter; applied once in final_kernel.
// Layout: exact-fit grid, ONE quad per thread, consecutive threads on
// consecutive quads (chip-wide interleave — measured faster than per-block
// contiguous slabs in R5: node arrays are L2-resident regardless, and slabs
// only added L1 thrash + per-block stream queueing).
__global__ void scatter_kernel(const float* __restrict__ h,
                               float* __restrict__ out,
                               const int4* __restrict__ src4,
                               const int4* __restrict__ dst4,
                               const float4* __restrict__ lew4,
                               int nquad,
                               const int* __restrict__ src_s,
                               const int* __restrict__ dst_s,
                               int ntail) {
    int i = blockIdx.x * blockDim.x + threadIdx.x;
    if (i < nquad) {
        int4   s = src4[i];
        int4   d = dst4[i];
        float4 w = lew4[i];
        atomicAdd(&out[d.x], h[s.x] * w.x);
        atomicAdd(&out[d.y], h[s.y] * w.y);
        atomicAdd(&out[d.z], h[s.z] * w.z);
        atomicAdd(&out[d.w], h[s.w] * w.w);
    } else if (i - nquad < ntail) {
        int e = nquad * 4 + (i - nquad);
        atomicAdd(&out[dst_s[e]], h[src_s[e]] * g_lew[e]);
    }
}

// ---------------------------------------------------------------------------
// Final: per graph (one block each): sumsq-reduce g_C over N nodes -> scale,
// gather decision neurons (scaled), nonzero-masked standardization, mean pool,
// linear + relu.
__global__ void final_kernel(const int* __restrict__ dm,
                             const float* __restrict__ fc_w,
                             const float* __restrict__ fc_b,
                             float* __restrict__ out,
                             int N, int M) {
    __shared__ float sv[M_MAX];
    __shared__ float red_f[256];
    __shared__ float red_g[256];
    __shared__ float s_scale, s_mean, s_inv_std, s_cnt;

    int b = blockIdx.x;
    int t = threadIdx.x;
    const float* h = g_C + b * N;

    // Phase 0: per-graph sum of squares (vectorized)
    float ss = 0.0f;
    int n4 = N >> 2;
    const float4* h4 = (const float4*)h;
    for (int i = t; i < n4; i += blockDim.x) {
        float4 v = h4[i];
        ss += v.x * v.x + v.y * v.y + v.z * v.z + v.w * v.w;
    }
    for (int i = n4 * 4 + t; i < N; i += blockDim.x) { float v = h[i]; ss += v * v; }
    red_f[t] = ss;
    __syncthreads();
    for (int off = 128; off > 0; off >>= 1) {
        if (t < off) red_f[t] += red_f[t + off];
        __syncthreads();
    }
    if (t == 0) s_scale = rsqrtf(red_f[0]);
    __syncthreads();
    float scale = s_scale;

    // Gather decision neurons, scaled by the (only surviving) normalization
    for (int m = t; m < M; m += blockDim.x)
        sv[m] = h[dm[m]] * scale;
    __syncthreads();

    // Reduction 1: nonzero count + sum
    float sum = 0.0f, cnt = 0.0f;
    for (int m = t; m < M; m += blockDim.x) {
        float v = sv[m];
        if (v != 0.0f) { sum += v; cnt += 1.0f; }
    }
    red_f[t] = sum; red_g[t] = cnt;
    __syncthreads();
    for (int off = 128; off > 0; off >>= 1) {
        if (t < off) { red_f[t] += red_f[t + off]; red_g[t] += red_g[t + off]; }
        __syncthreads();
    }
    if (t == 0) { s_cnt = red_g[0]; s_mean = red_f[0] / red_g[0]; }
    __syncthreads();
    float mean = s_mean, cntv = s_cnt;

    // Reduction 2: sum (v-mean)^2 over nonzeros
    float ss2 = 0.0f;
    for (int m = t; m < M; m += blockDim.x) {
        float v = sv[m];
        if (v != 0.0f) { float d = v - mean; ss2 += d * d; }
    }
    red_f[t] = ss2;
    __syncthreads();
    for (int off = 128; off > 0; off >>= 1) {
        if (t < off) red_f[t] += red_f[t + off];
        __syncthreads();
    }
    if (t == 0) {
        float var = red_f[0] / fmaxf(cntv - 1.0f, 1.0f);
        s_inv_std = 1.0f / (sqrtf(var) + 1e-5f);
    }
    __syncthreads();
    float inv_std = s_inv_std;

    // Reduction 3: sum of standardized values over nonzeros
    float ps = 0.0f;
    for (int m = t; m < M; m += blockDim.x) {
        float v = sv[m];
        if (v != 0.0f) ps += (v - mean) * inv_std;
    }
    red_f[t] = ps;
    __syncthreads();
    for (int off = 128; off > 0; off >>= 1) {
        if (t < off) red_f[t] += red_f[t + off];
        __syncthreads();
    }
    if (t == 0) {
        float pooled = red_f[0] / (float)M;
        float o = pooled * fc_w[0] + fc_b[0];
        out[b] = fmaxf(o, 0.0f);
    }
}

// ---------------------------------------------------------------------------
extern "C" void kernel_launch(void* const* d_in, const int* in_sizes, int n_in,
                              void* d_out, int out_size) {
    const float* x    = (const float*)d_in[0];
    const float* ew   = (const float*)d_in[1];
    const int*   src  = (const int*)d_in[2];
    const int*   dst  = (const int*)d_in[3];
    const int*   dm   = (const int*)d_in[4];
    const float* fc_w = (const float*)d_in[5];
    const float* fc_b = (const float*)d_in[6];
    float* out = (float*)d_out;

    int BN = in_sizes[0];
    int E  = in_sizes[1];
    int M  = in_sizes[4];
    int N  = BN / NUM_GRAPHS;

    // Device addresses of __device__ symbols (host-side &symbol is invalid!)
    static float *pA = nullptr, *pB = nullptr, *pC = nullptr, *pLEW = nullptr;
    if (pA == nullptr) {
        void* p;
        cudaGetSymbolAddress(&p, g_A);   pA   = (float*)p;
        cudaGetSymbolAddress(&p, g_B);   pB   = (float*)p;
        cudaGetSymbolAddress(&p, g_C);   pC   = (float*)p;
        cudaGetSymbolAddress(&p, g_lew); pLEW = (float*)p;
    }

    int nquad = E / 4;
    int ntail = E - nquad * 4;

    const int T = 256;
    int scatter_blocks = (nquad + ntail + T - 1) / T;

    init_kernel<<<2048, T>>>(ew, E, BN);

    // Raw (unnormalized) passes: normalization cancels through linear scatter.
    const float* srcbuf[NUM_PASSES + 1] = { x, pA, pB, pC };
    float*       dstbuf[NUM_PASSES]     = { pA, pB, pC };
    for (int p = 0; p < NUM_PASSES; p++) {
        scatter_kernel<<<scatter_blocks, T>>>(
            srcbuf[p], dstbuf[p],
            (const int4*)src, (const int4*)dst, (const float4*)pLEW,
            nquad, src, dst, ntail);
    }

    final_kernel<<<NUM_GRAPHS, 256>>>(dm, fc_w, fc_b, out, N, M);
}